// round 15
// baseline (speedup 1.0000x reference)
#include <cuda_runtime.h>
#include <cstdint>

#define NROWS 8192
#define DDIM  8192
#define KIN   1024
#define NT    128

typedef unsigned long long ull;

// ---- packed f32x2 helpers (Blackwell sm_103a) ----
__device__ __forceinline__ ull pack2(float lo, float hi) {
    ull r; asm("mov.b64 %0, {%1, %2};" : "=l"(r) : "f"(lo), "f"(hi)); return r;
}
__device__ __forceinline__ void unpack2(ull v, float& lo, float& hi) {
    asm("mov.b64 {%0, %1}, %2;" : "=f"(lo), "=f"(hi) : "l"(v));
}
__device__ __forceinline__ ull f2add(ull a, ull b) {
    ull r; asm("add.rn.f32x2 %0, %1, %2;" : "=l"(r) : "l"(a), "l"(b)); return r;
}
// a - b == fma(b, -1, a)
__device__ __forceinline__ ull f2sub(ull a, ull b) {
    const ull NEG1 = 0xBF800000BF800000ULL;
    ull r; asm("fma.rn.f32x2 %0, %1, %2, %3;" : "=l"(r) : "l"(b), "l"(NEG1), "l"(a)); return r;
}
__device__ __forceinline__ ull f2mul(ull a, ull b) {
    ull r; asm("mul.rn.f32x2 %0, %1, %2;" : "=l"(r) : "l"(a), "l"(b)); return r;
}
// a*b + c
__device__ __forceinline__ ull f2fma(ull a, ull b, ull c) {
    ull r; asm("fma.rn.f32x2 %0, %1, %2, %3;" : "=l"(r) : "l"(a), "l"(b), "l"(c)); return r;
}

// Storage swizzle: slot(e) = e ^ (((e>>7)&31)<<2)  (perturbs bits 2..6 only)
__device__ __forceinline__ int slot(int e) {
    return e ^ (((e >> 7) & 31) << 2);
}

// Guaranteed-predicated shared store (no BSSY/BSYNC divergence).
__device__ __forceinline__ void sts_pred(uint32_t addr, float v, int pred) {
    asm volatile(
        "{ .reg .pred p; setp.ne.s32 p, %2, 0; @p st.shared.f32 [%0], %1; }"
        :: "r"(addr), "f"(v), "r"(pred) : "memory");
}

__global__ void __launch_bounds__(NT, 5) fwht_kernel(
    const float* __restrict__ u, const int* __restrict__ idx, float* __restrict__ out)
{
    __shared__ float sm[DDIM];   // 32 KB, single in-place buffer
    float4* smv = reinterpret_cast<float4*>(sm);
    uint32_t smbase;
    asm("{ .reg .u64 q; cvta.to.shared.u64 q, %1; cvt.u32.u64 %0, q; }"
        : "=r"(smbase) : "l"(sm));

    const int t   = threadIdx.x;       // 0..127
    const int row = blockIdx.x;
    const float* urow = u + (long)row * KIN;

    // ---- early global loads (8 keys + 8 values + boundary peek) ----
    int4   iv[2];
    float4 uv[2];
    {
        const int4*   idx4 = reinterpret_cast<const int4*>(idx);
        const float4* u4   = reinterpret_cast<const float4*>(urow);
#pragma unroll
        for (int i = 0; i < 2; i++) { iv[i] = idx4[2 * t + i]; uv[i] = u4[2 * t + i]; }
    }
    const int j8 = 8 * t + 8;
    const int prev0  = (t == 0) ? -1 : idx[8 * t - 1];
    const int idnxt  = (j8     < KIN) ? idx[j8]     : -1;
    const int idnxt2 = (j8 + 1 < KIN) ? idx[j8 + 1] : -1;
    const float unxt = (j8     < KIN) ? urow[j8]    : 0.f;

    // ---- zero smem (32KB, STS.128, conflict-free), overlaps LDG latency ----
    const float4 z4 = make_float4(0.f, 0.f, 0.f, 0.f);
#pragma unroll
    for (int i = 0; i < DDIM / 4 / NT; i++) smv[t + NT * i] = z4;
    __syncthreads();

    // ---- scatter: backward run-sum scan + predicated leader stores ----
    {
        int   id[8]; float uu[8];
        id[0]=iv[0].x; id[1]=iv[0].y; id[2]=iv[0].z; id[3]=iv[0].w;
        id[4]=iv[1].x; id[5]=iv[1].y; id[6]=iv[1].z; id[7]=iv[1].w;
        uu[0]=uv[0].x; uu[1]=uv[0].y; uu[2]=uv[0].z; uu[3]=uv[0].w;
        uu[4]=uv[1].x; uu[5]=uv[1].y; uu[6]=uv[1].z; uu[7]=uv[1].w;

        float tail = (idnxt == id[7]) ? unxt : 0.f;
        if (idnxt == id[7] && idnxt2 == id[7]) {
            int j = j8 + 1;
            while (j < KIN && idx[j] == id[7]) { tail += urow[j]; j++; }
        }
        float s[8];
        s[7] = uu[7] + tail;
#pragma unroll
        for (int p = 6; p >= 0; p--)
            s[p] = uu[p] + ((id[p + 1] == id[p]) ? s[p + 1] : 0.f);
        int pv = prev0;
#pragma unroll
        for (int p = 0; p < 8; p++) {
            sts_pred(smbase + 4u * (uint32_t)slot(id[p]), s[p], id[p] != pv);
            pv = id[p];
        }
    }
    __syncthreads();

    // ==== Phase 1: thread owns e in [64t, 64t+64); bits 0..5 in regs, bit 6 via shfl ====
    // thread's quad c lives at float4-index 32*(t>>1) + ((16*(t&1) + c) ^ w5), w5=(t>>1)&31
    // -> 16x LDS.128, conflict-free for any c (verified per 8-lane phase)
    {
        const int w5 = (t >> 1) & 31;
        const int gb = 32 * (t >> 1);
        const int hb = 16 * (t & 1);
        ull y[32];
#pragma unroll
        for (int c = 0; c < 16; c++) {
            float4 q = smv[gb + ((hb + c) ^ w5)];
            y[2 * c]     = pack2(q.x + q.y, q.x - q.y);   // fold bit 0
            y[2 * c + 1] = pack2(q.z + q.w, q.z - q.w);
        }
        // bits 1..5: 5 packed stages over k = 0..31
#pragma unroll
        for (int m = 16; m >= 1; m >>= 1) {
#pragma unroll
            for (int j = 0; j < 32; j++) {
                if (!(j & m)) {
                    ull a = y[j], b = y[j | m];
                    y[j]     = f2add(a, b);
                    y[j | m] = f2sub(a, b);
                }
            }
        }
        // bit 6: butterfly with partner thread t^1 (same warp), branchless sign-FMA
        // even t: new = own + partner ; odd t: new = partner - own  => own*s + partner
        const float sgn = (t & 1) ? -1.f : 1.f;
        const ull  sp2 = pack2(sgn, sgn);
#pragma unroll
        for (int k = 0; k < 32; k++) {
            float lo, hi; unpack2(y[k], lo, hi);
            float plo = __shfl_xor_sync(0xFFFFFFFFu, lo, 1);
            float phi = __shfl_xor_sync(0xFFFFFFFFu, hi, 1);
            y[k] = f2fma(y[k], sp2, pack2(plo, phi));
        }
        // write back IN-PLACE (thread-exclusive slots, same addresses)
#pragma unroll
        for (int c = 0; c < 16; c++) {
            float a0, a1, b0, b1;
            unpack2(y[2 * c], a0, a1);
            unpack2(y[2 * c + 1], b0, b1);
            smv[gb + ((hb + c) ^ w5)] = make_float4(a0, a1, b0, b1);
        }
    }
    __syncthreads();   // P2 reads cross-thread

    // ==== Phase 2: tau = t; e = tau + 128m; fold bit 12 at load, stages bits 7..11 ====
    // slot = (t ^ ((m&31)<<2)) + 128m ; pairs (m, m+32) share the same XOR constant
    {
        ull z[32];
#pragma unroll
        for (int mp = 0; mp < 32; mp++) {
            const int xc = t ^ (mp << 2);           // mp<32 => (mp&31)=mp
            float a = sm[xc + 128 * mp];            // e = t + 128*mp
            float b = sm[xc + 128 * (mp + 32)];     // e = t + 128*(mp+32)
            z[mp] = pack2(a + b, a - b);            // fold bit 12
        }
        // bits 7..11: 5 packed stages over mp = 0..31
#pragma unroll
        for (int mm = 16; mm >= 1; mm >>= 1) {
#pragma unroll
            for (int j = 0; j < 32; j++) {
                if (!(j & mm)) {
                    ull a = z[j], b = z[j | mm];
                    z[j]      = f2add(a, b);
                    z[j | mm] = f2sub(a, b);
                }
            }
        }
        // scale + store: lo -> orow[t + 128mp], hi -> orow[t + 128mp + 4096]; coalesced
        const float SCALE = 0.011048543456039806f;  // 1/sqrt(8192)
        const ull SC2 = pack2(SCALE, SCALE);
        float* orow = out + (long)row * DDIM;
#pragma unroll
        for (int mp = 0; mp < 32; mp++) {
            float lo, hi;
            unpack2(f2mul(z[mp], SC2), lo, hi);
            orow[t + 128 * mp]        = lo;
            orow[t + 128 * mp + 4096] = hi;
        }
    }
}

extern "C" void kernel_launch(void* const* d_in, const int* in_sizes, int n_in,
                              void* d_out, int out_size)
{
    const float* u   = (const float*)d_in[0];
    const int*   idx = (const int*)d_in[1];
    float*       out = (float*)d_out;
    fwht_kernel<<<NROWS, NT>>>(u, idx, out);
}

// round 16
// speedup vs baseline: 1.0616x; 1.0616x over previous
#include <cuda_runtime.h>
#include <cstdint>

#define NROWS 8192
#define DDIM  8192
#define KIN   1024
#define NT    64

typedef unsigned long long ull;

// ---- packed f32x2 helpers (Blackwell sm_103a) ----
__device__ __forceinline__ ull pack2(float lo, float hi) {
    ull r; asm("mov.b64 %0, {%1, %2};" : "=l"(r) : "f"(lo), "f"(hi)); return r;
}
__device__ __forceinline__ void unpack2(ull v, float& lo, float& hi) {
    asm("mov.b64 {%0, %1}, %2;" : "=f"(lo), "=f"(hi) : "l"(v));
}
__device__ __forceinline__ ull f2add(ull a, ull b) {
    ull r; asm("add.rn.f32x2 %0, %1, %2;" : "=l"(r) : "l"(a), "l"(b)); return r;
}
// a - b == fma(b, -1, a)
__device__ __forceinline__ ull f2sub(ull a, ull b) {
    const ull NEG1 = 0xBF800000BF800000ULL;
    ull r; asm("fma.rn.f32x2 %0, %1, %2, %3;" : "=l"(r) : "l"(b), "l"(NEG1), "l"(a)); return r;
}
__device__ __forceinline__ ull f2mul(ull a, ull b) {
    ull r; asm("mul.rn.f32x2 %0, %1, %2;" : "=l"(r) : "l"(a), "l"(b)); return r;
}

// Storage swizzle: slot(e) = e ^ (((e>>7)&31)<<2)  (perturbs bits 2..6 only;
// quad identity preserved: quad(e) -> quad(e) ^ w5 within the same 128-block)
__device__ __forceinline__ int slot(int e) {
    return e ^ (((e >> 7) & 31) << 2);
}

// Predicated shared ops (guaranteed no BSSY/BSYNC)
__device__ __forceinline__ void sts_pred(uint32_t addr, float v, int pred) {
    asm volatile(
        "{ .reg .pred p; setp.ne.s32 p, %2, 0; @p st.shared.f32 [%0], %1; }"
        :: "r"(addr), "f"(v), "r"(pred) : "memory");
}
__device__ __forceinline__ void sts128_zero_pred(uint32_t addr, unsigned pred) {
    asm volatile(
        "{ .reg .pred p; setp.ne.u32 p, %1, 0;\n\t"
        "@p st.shared.v4.f32 [%0], {0f00000000, 0f00000000, 0f00000000, 0f00000000}; }"
        :: "r"(addr), "r"(pred) : "memory");
}
__device__ __forceinline__ float4 lds128_or_zero(uint32_t addr, unsigned pred) {
    float4 q;
    asm volatile(
        "{ .reg .pred p; setp.ne.u32 p, %5, 0;\n\t"
        "mov.f32 %0, 0f00000000; mov.f32 %1, 0f00000000;\n\t"
        "mov.f32 %2, 0f00000000; mov.f32 %3, 0f00000000;\n\t"
        "@p ld.shared.v4.f32 {%0, %1, %2, %3}, [%4]; }"
        : "=f"(q.x), "=f"(q.y), "=f"(q.z), "=f"(q.w)
        : "r"(addr), "r"(pred));
    return q;
}

__global__ void __launch_bounds__(NT, 6) fwht_kernel(
    const float* __restrict__ u, const int* __restrict__ idx, float* __restrict__ out)
{
    __shared__ float    sm[DDIM];       // 32 KB exchange buffer (never globally zeroed)
    __shared__ unsigned qoccW[512];     // 2 KB: qocc[q] (byte) = quad q has >=1 key
    float4* smv = reinterpret_cast<float4*>(sm);
    unsigned char* qocc = reinterpret_cast<unsigned char*>(qoccW);
    uint32_t smbase;
    asm("{ .reg .u64 q; cvta.to.shared.u64 q, %1; cvt.u32.u64 %0, q; }"
        : "=r"(smbase) : "l"(sm));

    const int t   = threadIdx.x;       // 0..63
    const int row = blockIdx.x;
    const float* urow = u + (long)row * KIN;

    // ---- early global loads (16 keys + 16 values + boundary peek) ----
    int4   iv[4];
    float4 uv[4];
    {
        const int4*   idx4 = reinterpret_cast<const int4*>(idx);
        const float4* u4   = reinterpret_cast<const float4*>(urow);
#pragma unroll
        for (int i = 0; i < 4; i++) { iv[i] = idx4[4 * t + i]; uv[i] = u4[4 * t + i]; }
    }
    const int j16 = 16 * t + 16;
    const int prev0  = (t == 0) ? -1 : idx[16 * t - 1];
    const int idnxt  = (j16     < KIN) ? idx[j16]     : -1;
    const int idnxt2 = (j16 + 1 < KIN) ? idx[j16 + 1] : -1;
    const float unxt = (j16     < KIN) ? urow[j16]    : 0.f;

    int   id[16]; float uu[16];
#pragma unroll
    for (int i = 0; i < 4; i++) {
        id[4*i] = iv[i].x; id[4*i+1] = iv[i].y; id[4*i+2] = iv[i].z; id[4*i+3] = iv[i].w;
        uu[4*i] = uv[i].x; uu[4*i+1] = uv[i].y; uu[4*i+2] = uv[i].z; uu[4*i+3] = uv[i].w;
    }

    // ---- (1) clear quad-occupancy bytes (2 KB total, 8 words/thread) ----
    {
        uint4* qv = reinterpret_cast<uint4*>(qoccW);
        const uint4 z0 = make_uint4(0u, 0u, 0u, 0u);
        qv[2 * t]     = z0;
        qv[2 * t + 1] = z0;
    }
    __syncthreads();

    // ---- (2) mark each key's quad: plain idempotent byte stores (no atomics) ----
#pragma unroll
    for (int p = 0; p < 16; p++)
        qocc[id[p] >> 2] = 1;
    __syncthreads();

    // ---- (3) read own 32 quad-occupancy bytes; pre-zero ONLY occupied quads ----
    const int tm = t & 31;
    const int qb = t << 5;               // float4-index base of this thread's 32 quads
    unsigned ow[8];
    {
        const uint4* qv = reinterpret_cast<const uint4*>(qoccW);
        uint4 a = qv[2 * t], b = qv[2 * t + 1];
        ow[0]=a.x; ow[1]=a.y; ow[2]=a.z; ow[3]=a.w;
        ow[4]=b.x; ow[5]=b.y; ow[6]=b.z; ow[7]=b.w;
    }
#pragma unroll
    for (int c = 0; c < 32; c++) {
        unsigned pred = (ow[c >> 2] >> (8 * (c & 3))) & 0xFFu;
        sts128_zero_pred(smbase + ((qb + (c ^ tm)) << 4), pred);
    }
    __syncthreads();   // occupied quads zeroed before cross-thread scatter

    // ---- (4) scatter: backward run-sum scan + predicated leader stores ----
    {
        float tail = (idnxt == id[15]) ? unxt : 0.f;
        if (idnxt == id[15] && idnxt2 == id[15]) {
            int j = j16 + 1;
            while (j < KIN && idx[j] == id[15]) { tail += urow[j]; j++; }
        }
        float s[16];
        s[15] = uu[15] + tail;
#pragma unroll
        for (int p = 14; p >= 0; p--)
            s[p] = uu[p] + ((id[p + 1] == id[p]) ? s[p + 1] : 0.f);
        int pv = prev0;
#pragma unroll
        for (int p = 0; p < 16; p++) {
            sts_pred(smbase + 4u * (uint32_t)slot(id[p]), s[p], id[p] != pv);
            pv = id[p];
        }
    }
    __syncthreads();

    // ==== Phase 1: thread owns e in [128t, 128t+128); bits 0..6 in registers ====
    // occupied quads loaded, unoccupied quads are implicit zeros (no wavefronts)
    {
        ull y[64];
#pragma unroll
        for (int c = 0; c < 32; c++) {
            unsigned pred = (ow[c >> 2] >> (8 * (c & 3))) & 0xFFu;
            float4 q = lds128_or_zero(smbase + ((qb + (c ^ tm)) << 4), pred);
            y[2 * c]     = pack2(q.x + q.y, q.x - q.y);   // fold bit 0
            y[2 * c + 1] = pack2(q.z + q.w, q.z - q.w);
        }
        // bits 1..6: 6 packed stages over pair-index p = 0..63
#pragma unroll
        for (int m = 32; m >= 1; m >>= 1) {
#pragma unroll
            for (int j = 0; j < 64; j++) {
                if (!(j & m)) {
                    ull a = y[j], b = y[j | m];
                    y[j]     = f2add(a, b);
                    y[j | m] = f2sub(a, b);
                }
            }
        }
        // write back IN-PLACE, DENSE (valid data everywhere; garbage never escapes)
#pragma unroll
        for (int c = 0; c < 32; c++) {
            float a0, a1, b0, b1;
            unpack2(y[2 * c], a0, a1);
            unpack2(y[2 * c + 1], b0, b1);
            smv[qb + (c ^ tm)] = make_float4(a0, a1, b0, b1);
        }
    }
    __syncthreads();   // P2 reads cross-thread

    // ==== Phase 2: bits 7..12; thread handles tau pair (2t, 2t+1), single pass ====
    // read e = tau + 128m at slot = 128m + (tau ^ ((m&31)<<2)); tau pair adjacent -> LDS.64
    {
        ull z[64];
        const int t2 = 2 * t;
#pragma unroll
        for (int m = 0; m < 64; m++) {
            float2 v = *reinterpret_cast<const float2*>(
                &sm[128 * m + (t2 ^ ((m & 31) << 2))]);
            z[m] = pack2(v.x, v.y);   // packed lanes = (tau0, tau1)
        }
        // 6 packed stages over m (bits 7..12)
#pragma unroll
        for (int mm = 32; mm >= 1; mm >>= 1) {
#pragma unroll
            for (int j = 0; j < 64; j++) {
                if (!(j & mm)) {
                    ull a = z[j], b = z[j | mm];
                    z[j]      = f2add(a, b);
                    z[j | mm] = f2sub(a, b);
                }
            }
        }
        // scale + store: float2 at orow[128m + 2t]  -> STG.64, coalesced
        const float SCALE = 0.011048543456039806f;  // 1/sqrt(8192)
        const ull SC2 = pack2(SCALE, SCALE);
        float2* orow2 = reinterpret_cast<float2*>(out + (long)row * DDIM);
#pragma unroll
        for (int m = 0; m < 64; m++) {
            float lo, hi;
            unpack2(f2mul(z[m], SC2), lo, hi);
            orow2[64 * m + t] = make_float2(lo, hi);
        }
    }
}

extern "C" void kernel_launch(void* const* d_in, const int* in_sizes, int n_in,
                              void* d_out, int out_size)
{
    const float* u   = (const float*)d_in[0];
    const int*   idx = (const int*)d_in[1];
    float*       out = (float*)d_out;
    fwht_kernel<<<NROWS, NT>>>(u, idx, out);
}